// round 12
// baseline (speedup 1.0000x reference)
#include <cuda_runtime.h>
#include <cstdint>

// B=16, H=128, W=128, C=256, P=8192
//   in_tensor: (B,H,W,C) f32   indices: (B,P,2) f32 (dim0->H, dim1->W)
//   out: (B,P,C) f32
//
// Bilinear: out = p1*(1-mx)(1-my) + p2*mx(1-my) + p3*(1-mx)my + p4*mx*my
//
// R11 findings: warp-specialized TMA ring has plenty of buffered demand but
// DRAM stuck ~70%. Diagnosis: NITER=16 vs 5-stage ring -> ~25-30% of each
// CTA's life is pipeline fill/drain, x4096 CTA lifetimes + ~5.5 waves of
// transitions. Fix: PERSISTENT kernel. Exactly the resident set (740 CTAs =
// 5/SM x 148) each streams ~88 stage-groups through one continuously-full
// ring; fill/drain amortizes to zero, no wave transitions.

#define GB 16
#define GH 128
#define GW 128
#define GC 256
#define GP 8192

#define NTHREADS 160            // warps 0-3: consumers, warp 4: producer
#define NCTA 740                // 5 CTAs/SM x 148 SMs (resident set)
#define STAGES 5
#define PTS_PER_STAGE 2
#define TOTAL_GROUPS ((GB * GP) / PTS_PER_STAGE)     // 65536
#define ROW_BYTES (GC * 4)                           // 1024
#define IMG_BYTES ((size_t)GH * GW * ROW_BYTES)
#define STAGE_BYTES (PTS_PER_STAGE * 4 * ROW_BYTES)  // 8192

__device__ __forceinline__ uint32_t smem_u32(const void* p) {
    uint32_t a;
    asm("{ .reg .u64 t; cvta.to.shared.u64 t, %1; cvt.u32.u64 %0, t; }"
        : "=r"(a) : "l"(p));
    return a;
}

__device__ __forceinline__ void mbar_init(uint32_t bar, uint32_t count) {
    asm volatile("mbarrier.init.shared.b64 [%0], %1;" :: "r"(bar), "r"(count) : "memory");
}

__device__ __forceinline__ void mbar_arrive(uint32_t bar) {
    asm volatile("mbarrier.arrive.shared.b64 _, [%0];" :: "r"(bar) : "memory");
}

__device__ __forceinline__ void mbar_expect_tx(uint32_t bar, uint32_t bytes) {
    asm volatile("mbarrier.arrive.expect_tx.shared.b64 _, [%0], %1;"
                 :: "r"(bar), "r"(bytes) : "memory");
}

__device__ __forceinline__ void bulk_g2s(uint32_t dst, const void* src,
                                         uint32_t bytes, uint32_t bar) {
    asm volatile(
        "cp.async.bulk.shared::cta.global.mbarrier::complete_tx::bytes "
        "[%0], [%1], %2, [%3];"
        :: "r"(dst), "l"(src), "r"(bytes), "r"(bar) : "memory");
}

__device__ __forceinline__ void mbar_wait(uint32_t bar, uint32_t parity) {
    asm volatile(
        "{\n\t"
        ".reg .pred P;\n\t"
        "WAIT_%=:\n\t"
        "mbarrier.try_wait.parity.acquire.cta.shared::cta.b64 P, [%0], %1, 0x989680;\n\t"
        "@P bra DONE_%=;\n\t"
        "bra WAIT_%=;\n\t"
        "DONE_%=:\n\t"
        "}"
        :: "r"(bar), "r"(parity) : "memory");
}

__global__ __launch_bounds__(NTHREADS) void grid_sample_tma(
    const float* __restrict__ in_tensor,
    const float* __restrict__ indices,
    float* __restrict__ out)
{
    __shared__ alignas(16) unsigned char stage_buf[STAGES * STAGE_BYTES];
    __shared__ alignas(8)  unsigned long long full_bar[STAGES];
    __shared__ alignas(8)  unsigned long long empty_bar[STAGES];

    const int tid = threadIdx.x;
    const int cta = blockIdx.x;

    const uint32_t fbar0 = smem_u32(&full_bar[0]);
    const uint32_t ebar0 = smem_u32(&empty_bar[0]);
    const uint32_t sbuf0 = smem_u32(&stage_buf[0]);

    if (tid == 0) {
        #pragma unroll
        for (int s = 0; s < STAGES; s++) {
            mbar_init(fbar0 + s * 8, 1);   // 1 arrive: producer's expect_tx
            mbar_init(ebar0 + s * 8, 4);   // 4 arrives: one per consumer warp
        }
    }
    __syncthreads();

    const float2* idx2 = (const float2*)indices;
    const char*   img0 = (const char*)in_tensor;

    if (tid >= 128) {
        // ── Producer warp: 8 active lanes, one 1KB bulk copy each ──────
        const int t = tid - 128;
        if (t < 8) {
            const int pk     = t >> 2;    // point within stage (0/1)
            const int corner = t & 3;     // which corner row
            int stage = 0, phase = 1;     // phase=1: first empty-wait passes
            for (int g = cta; g < TOTAL_GROUPS; g += NCTA) {
                const uint32_t eb = ebar0 + stage * 8;
                const uint32_t fb = fbar0 + stage * 8;
                mbar_wait(eb, phase);
                if (t == 0) mbar_expect_tx(fb, STAGE_BYTES);
                __syncwarp(0x000000FFu);  // expect_tx posted before copies
                const int point = g * PTS_PER_STAGE + pk;
                const float2 ind = __ldg(idx2 + point);
                const int b = point >> 13;
                const float fx = floorf(ind.x);
                const float fy = floorf(ind.y);
                const int row  = (int)fx * GW + (int)fy;
                // ceil==floor when coord integral (weight 0) -> delta 0 exact
                const int dh = (ind.x > fx) ? (GW * ROW_BYTES) : 0;
                const int dw = (ind.y > fy) ? ROW_BYTES : 0;
                const int off = (corner & 1 ? dh : 0) + (corner & 2 ? dw : 0);
                const char* src = img0 + (size_t)b * IMG_BYTES
                                + (size_t)row * ROW_BYTES + off;
                bulk_g2s(sbuf0 + stage * STAGE_BYTES + (pk * 4 + corner) * ROW_BYTES,
                         src, ROW_BYTES, fb);
                if (++stage == STAGES) { stage = 0; phase ^= 1; }
            }
        }
    } else {
        // ── Consumer warps: 128 threads, 64 per point ─────────────────
        const int k    = tid >> 6;        // point within stage (0/1)
        const int slot = tid & 63;        // float4 slot in C=256 row
        const int lane = tid & 31;
        float4* out4 = (float4*)out;

        int stage = 0, phase = 0;
        for (int g = cta; g < TOTAL_GROUPS; g += NCTA) {
            const int point = g * PTS_PER_STAGE + k;
            const float2 ind = __ldg(idx2 + point);   // issue before wait

            const uint32_t fb = fbar0 + stage * 8;
            const uint32_t eb = ebar0 + stage * 8;
            mbar_wait(fb, phase);

            const float mx = ind.x - floorf(ind.x);
            const float my = ind.y - floorf(ind.y);
            const float omx = 1.0f - mx;
            const float omy = 1.0f - my;
            const float w1 = omx * omy;
            const float w2 = mx  * omy;
            const float w3 = omx * my;
            const float w4 = mx  * my;

            const float4* sb = (const float4*)(stage_buf + stage * STAGE_BYTES
                                               + k * 4 * ROW_BYTES);
            const float4 v1 = sb[slot];
            const float4 v2 = sb[64 + slot];
            const float4 v3 = sb[128 + slot];
            const float4 v4 = sb[192 + slot];

            float4 o;
            o.x = v1.x * w1 + v2.x * w2 + v3.x * w3 + v4.x * w4;
            o.y = v1.y * w1 + v2.y * w2 + v3.y * w3 + v4.y * w4;
            o.z = v1.z * w1 + v2.z * w2 + v3.z * w3 + v4.z * w4;
            o.w = v1.w * w1 + v2.w * w2 + v3.w * w3 + v4.w * w4;

            __stcs(out4 + (size_t)point * (GC / 4) + slot, o);

            __syncwarp();                 // all lanes done reading stage
            if (lane == 0) mbar_arrive(eb);

            if (++stage == STAGES) { stage = 0; phase ^= 1; }
        }
    }
}

extern "C" void kernel_launch(void* const* d_in, const int* in_sizes, int n_in,
                              void* d_out, int out_size)
{
    const float* in_tensor = (const float*)d_in[0];
    const float* indices   = (const float*)d_in[1];
    float*       out       = (float*)d_out;

    grid_sample_tma<<<NCTA, NTHREADS>>>(in_tensor, indices, out);
}

// round 15
// speedup vs baseline: 1.2549x; 1.2549x over previous
#include <cuda_runtime.h>
#include <cstdint>

// B=16, H=128, W=128, C=256, P=8192
//   in_tensor: (B,H,W,C) f32   indices: (B,P,2) f32 (dim0->H, dim1->W)
//   out: (B,P,C) f32
//
// Bilinear: out = p1*(1-mx)(1-my) + p2*mx(1-my) + p3*(1-mx)my + p4*mx*my
//
// R12 lesson: persistent CTAs regressed badly — cross-CTA churn (6 resident
// CTAs/SM, 4096 total) is what overlaps ring fill/drain. This is the best
// structure (R10: 4-stage coupled ring, 4096 CTAs) with ONE change: the
// per-stage refill is issued by 8 lanes in parallel (one 1KB cp.async.bulk
// each) instead of serially by tid 0, taking 8 serial issue latencies off the
// stage-refill critical path. (Resubmit: R13/14 hit broker infra failures.)

#define GB 16
#define GH 128
#define GW 128
#define GC 256
#define GP 8192

#define NTHREADS 128
#define PPC 32                 // points per CTA (all same batch: 32 | 8192)
#define STAGES 4
#define PTS_PER_STAGE 2
#define NITER (PPC / PTS_PER_STAGE)          // 16
#define ROW_BYTES (GC * 4)                   // 1024
#define STAGE_BYTES (PTS_PER_STAGE * 4 * ROW_BYTES)  // 8192

__device__ __forceinline__ uint32_t smem_u32(const void* p) {
    uint32_t a;
    asm("{ .reg .u64 t; cvta.to.shared.u64 t, %1; cvt.u32.u64 %0, t; }"
        : "=r"(a) : "l"(p));
    return a;
}

__device__ __forceinline__ void mbar_init(uint32_t bar, uint32_t count) {
    asm volatile("mbarrier.init.shared.b64 [%0], %1;" :: "r"(bar), "r"(count) : "memory");
}

__device__ __forceinline__ void mbar_expect_tx(uint32_t bar, uint32_t bytes) {
    asm volatile("mbarrier.arrive.expect_tx.shared.b64 _, [%0], %1;"
                 :: "r"(bar), "r"(bytes) : "memory");
}

__device__ __forceinline__ void bulk_g2s(uint32_t dst, const void* src,
                                         uint32_t bytes, uint32_t bar) {
    asm volatile(
        "cp.async.bulk.shared::cta.global.mbarrier::complete_tx::bytes "
        "[%0], [%1], %2, [%3];"
        :: "r"(dst), "l"(src), "r"(bytes), "r"(bar) : "memory");
}

__device__ __forceinline__ void mbar_wait(uint32_t bar, uint32_t parity) {
    asm volatile(
        "{\n\t"
        ".reg .pred P;\n\t"
        "WAIT_%=:\n\t"
        "mbarrier.try_wait.parity.acquire.cta.shared::cta.b64 P, [%0], %1, 0x989680;\n\t"
        "@P bra DONE_%=;\n\t"
        "bra WAIT_%=;\n\t"
        "DONE_%=:\n\t"
        "}"
        :: "r"(bar), "r"(parity) : "memory");
}

__global__ __launch_bounds__(NTHREADS) void grid_sample_tma(
    const float* __restrict__ in_tensor,
    const float* __restrict__ indices,
    float* __restrict__ out)
{
    __shared__ alignas(16) unsigned char stage_buf[STAGES * STAGE_BYTES];
    __shared__ alignas(8)  unsigned long long mbar[STAGES];
    __shared__ float2 sidx[PPC];

    const int tid    = threadIdx.x;
    const int cta    = blockIdx.x;
    const int point0 = cta * PPC;                  // global first point
    const int b      = point0 >> 13;               // batch (constant per CTA)

    if (tid < PPC)
        sidx[tid] = __ldg(((const float2*)indices) + point0 + tid);

    const uint32_t mbar0 = smem_u32(&mbar[0]);
    const uint32_t sbuf0 = smem_u32(&stage_buf[0]);

    if (tid == 0) {
        #pragma unroll
        for (int s = 0; s < STAGES; s++) mbar_init(mbar0 + s * 8, 1);
    }
    __syncthreads();   // mbar init + sidx visible to all

    const char* img = (const char*)in_tensor + (size_t)b * (GH * GW) * ROW_BYTES;

    // Parallel refill: lanes 0-7 each issue one 1KB bulk copy for stage it&3.
    // Lane 0 posts expect_tx first; __syncwarp orders it before the copies.
    // Caller guarantees (via __syncthreads) that the slot is fully consumed.
    auto issue8 = [&](int it) {
        const int s = it & (STAGES - 1);
        const uint32_t bar = mbar0 + s * 8;
        if (tid == 0) mbar_expect_tx(bar, STAGE_BYTES);
        __syncwarp(0x000000FFu);
        const int pk     = tid >> 2;    // point within stage (0/1)
        const int corner = tid & 3;     // corner row
        const float2 ind = sidx[it * PTS_PER_STAGE + pk];
        const float fx = floorf(ind.x);
        const float fy = floorf(ind.y);
        const int row  = (int)fx * GW + (int)fy;
        // ceil==floor when coord integral (weight 0) -> delta 0 exact
        const int dh = (ind.x > fx) ? (GW * ROW_BYTES) : 0;
        const int dw = (ind.y > fy) ? ROW_BYTES : 0;
        const int off = (corner & 1 ? dh : 0) + (corner & 2 ? dw : 0);
        bulk_g2s(sbuf0 + s * STAGE_BYTES + (pk * 4 + corner) * ROW_BYTES,
                 img + (size_t)row * ROW_BYTES + off, ROW_BYTES, bar);
    };

    // Prologue: fill the ring (lanes 0-7)
    if (tid < 8) {
        #pragma unroll
        for (int it = 0; it < STAGES; it++) issue8(it);
    }

    // Consumers: 2 points/stage, 64 threads each (one float4 slot)
    const int k    = tid >> 6;        // point within stage (0/1)
    const int slot = tid & 63;        // float4 slot in C=256 row

    float4* out4 = (float4*)out;

    for (int it = 0; it < NITER; it++) {
        const int s  = it & (STAGES - 1);
        const int ph = (it >> 2) & 1;
        mbar_wait(mbar0 + s * 8, ph);

        const int p = it * PTS_PER_STAGE + k;
        const float2 ind = sidx[p];
        const float mx = ind.x - floorf(ind.x);
        const float my = ind.y - floorf(ind.y);
        const float omx = 1.0f - mx;
        const float omy = 1.0f - my;
        const float w1 = omx * omy;
        const float w2 = mx  * omy;
        const float w3 = omx * my;
        const float w4 = mx  * my;

        const float4* sb = (const float4*)(stage_buf + s * STAGE_BYTES + k * 4 * ROW_BYTES);
        const float4 v1 = sb[slot];
        const float4 v2 = sb[64 + slot];
        const float4 v3 = sb[128 + slot];
        const float4 v4 = sb[192 + slot];

        float4 o;
        o.x = v1.x * w1 + v2.x * w2 + v3.x * w3 + v4.x * w4;
        o.y = v1.y * w1 + v2.y * w2 + v3.y * w3 + v4.y * w4;
        o.z = v1.z * w1 + v2.z * w2 + v3.z * w3 + v4.z * w4;
        o.w = v1.w * w1 + v2.w * w2 + v3.w * w3 + v4.w * w4;

        __stcs(out4 + (size_t)(point0 + p) * (GC / 4) + slot, o);

        __syncthreads();                        // stage s fully consumed
        if (tid < 8 && it + STAGES < NITER) issue8(it + STAGES);
    }
}

extern "C" void kernel_launch(void* const* d_in, const int* in_sizes, int n_in,
                              void* d_out, int out_size)
{
    const float* in_tensor = (const float*)d_in[0];
    const float* indices   = (const float*)d_in[1];
    float*       out       = (float*)d_out;

    const int blocks = (GB * GP) / PPC;   // 131072/32 = 4096
    grid_sample_tma<<<blocks, NTHREADS>>>(in_tensor, indices, out);
}

// round 16
// speedup vs baseline: 1.2923x; 1.0299x over previous
#include <cuda_runtime.h>
#include <cstdint>

// B=16, H=128, W=128, C=256, P=8192
//   in_tensor: (B,H,W,C) f32   indices: (B,P,2) f32 (dim0->H, dim1->W)
//   out: (B,P,C) f32
//
// Bilinear: out = p1*(1-mx)(1-my) + p2*mx(1-my) + p3*(1-mx)my + p4*mx*my
//
// R15 finding: DRAM pinned at ~70% across all scheduling variants; traffic at
// floor. New lever: burst efficiency. indices < 127 strictly => floor_w <= 126
// and floor_h <= 126, so cells (fw, fw+1) are ALWAYS a contiguous, in-bounds
// 2KB span for both h-rows. Merge 4x1KB corner copies into 2x2KB copies per
// point: same bytes, half the random-chunk count, 2x DRAM burst length.
// (Integral coord => extra cell has weight 0; still correct.)

#define GB 16
#define GH 128
#define GW 128
#define GC 256
#define GP 8192

#define NTHREADS 128
#define PPC 32                 // points per CTA (all same batch: 32 | 8192)
#define STAGES 4
#define PTS_PER_STAGE 2
#define NITER (PPC / PTS_PER_STAGE)          // 16
#define ROW_BYTES (GC * 4)                   // 1024 (one cell)
#define PAIR_BYTES (2 * ROW_BYTES)           // 2048 (two w-adjacent cells)
#define STAGE_BYTES (PTS_PER_STAGE * 2 * PAIR_BYTES)  // 8192

__device__ __forceinline__ uint32_t smem_u32(const void* p) {
    uint32_t a;
    asm("{ .reg .u64 t; cvta.to.shared.u64 t, %1; cvt.u32.u64 %0, t; }"
        : "=r"(a) : "l"(p));
    return a;
}

__device__ __forceinline__ void mbar_init(uint32_t bar, uint32_t count) {
    asm volatile("mbarrier.init.shared.b64 [%0], %1;" :: "r"(bar), "r"(count) : "memory");
}

__device__ __forceinline__ void mbar_expect_tx(uint32_t bar, uint32_t bytes) {
    asm volatile("mbarrier.arrive.expect_tx.shared.b64 _, [%0], %1;"
                 :: "r"(bar), "r"(bytes) : "memory");
}

__device__ __forceinline__ void bulk_g2s(uint32_t dst, const void* src,
                                         uint32_t bytes, uint32_t bar) {
    asm volatile(
        "cp.async.bulk.shared::cta.global.mbarrier::complete_tx::bytes "
        "[%0], [%1], %2, [%3];"
        :: "r"(dst), "l"(src), "r"(bytes), "r"(bar) : "memory");
}

__device__ __forceinline__ void mbar_wait(uint32_t bar, uint32_t parity) {
    asm volatile(
        "{\n\t"
        ".reg .pred P;\n\t"
        "WAIT_%=:\n\t"
        "mbarrier.try_wait.parity.acquire.cta.shared::cta.b64 P, [%0], %1, 0x989680;\n\t"
        "@P bra DONE_%=;\n\t"
        "bra WAIT_%=;\n\t"
        "DONE_%=:\n\t"
        "}"
        :: "r"(bar), "r"(parity) : "memory");
}

__global__ __launch_bounds__(NTHREADS) void grid_sample_tma(
    const float* __restrict__ in_tensor,
    const float* __restrict__ indices,
    float* __restrict__ out)
{
    __shared__ alignas(16) unsigned char stage_buf[STAGES * STAGE_BYTES];
    __shared__ alignas(8)  unsigned long long mbar[STAGES];
    __shared__ float2 sidx[PPC];

    const int tid    = threadIdx.x;
    const int cta    = blockIdx.x;
    const int point0 = cta * PPC;                  // global first point
    const int b      = point0 >> 13;               // batch (constant per CTA)

    if (tid < PPC)
        sidx[tid] = __ldg(((const float2*)indices) + point0 + tid);

    const uint32_t mbar0 = smem_u32(&mbar[0]);
    const uint32_t sbuf0 = smem_u32(&stage_buf[0]);

    if (tid == 0) {
        #pragma unroll
        for (int s = 0; s < STAGES; s++) mbar_init(mbar0 + s * 8, 1);
    }
    __syncthreads();   // mbar init + sidx visible to all

    const char* img = (const char*)in_tensor + (size_t)b * (GH * GW) * ROW_BYTES;

    // Refill stage it&3: 4 lanes, each one 2KB bulk copy
    //   lane t: pk = t>>1 (point in stage), r = t&1 (h-row: floor / floor+1)
    //   copies cells [(fh+r, fw), (fh+r, fw+1)] = contiguous 2KB, in-bounds.
    auto issue4 = [&](int it) {
        const int s = it & (STAGES - 1);
        const uint32_t bar = mbar0 + s * 8;
        if (tid == 0) mbar_expect_tx(bar, STAGE_BYTES);
        __syncwarp(0x0000000Fu);        // expect_tx posted before copies
        const int pk = tid >> 1;
        const int r  = tid & 1;
        const float2 ind = sidx[it * PTS_PER_STAGE + pk];
        const int ifx = (int)floorf(ind.x);    // <= 126
        const int ify = (int)floorf(ind.y);    // <= 126
        const size_t cell = (size_t)(ifx + r) * GW + ify;
        bulk_g2s(sbuf0 + s * STAGE_BYTES + (pk * 2 + r) * PAIR_BYTES,
                 img + cell * ROW_BYTES, PAIR_BYTES, bar);
    };

    // Prologue: fill the ring (lanes 0-3)
    if (tid < 4) {
        #pragma unroll
        for (int it = 0; it < STAGES; it++) issue4(it);
    }

    // Consumers: 2 points/stage, 64 threads each (one float4 slot)
    const int k    = tid >> 6;        // point within stage (0/1)
    const int slot = tid & 63;        // float4 slot in C=256 row

    float4* out4 = (float4*)out;

    for (int it = 0; it < NITER; it++) {
        const int s  = it & (STAGES - 1);
        const int ph = (it >> 2) & 1;
        mbar_wait(mbar0 + s * 8, ph);

        const int p = it * PTS_PER_STAGE + k;
        const float2 ind = sidx[p];
        const float mx = ind.x - floorf(ind.x);
        const float my = ind.y - floorf(ind.y);
        const float omx = 1.0f - mx;
        const float omy = 1.0f - my;
        const float w1 = omx * omy;   // (fh, fw)
        const float w2 = mx  * omy;   // (fh+1, fw)
        const float w3 = omx * my;    // (fh, fw+1)
        const float w4 = mx  * my;    // (fh+1, fw+1)

        // Stage layout per point (float4 units, 64 per cell):
        //   [0,64)=p1 (fh,fw)  [64,128)=p3 (fh,fw+1)
        //   [128,192)=p2 (fh+1,fw)  [192,256)=p4 (fh+1,fw+1)
        const float4* sb = (const float4*)(stage_buf + s * STAGE_BYTES
                                           + k * 2 * PAIR_BYTES);
        const float4 v1 = sb[slot];
        const float4 v3 = sb[64 + slot];
        const float4 v2 = sb[128 + slot];
        const float4 v4 = sb[192 + slot];

        float4 o;
        o.x = v1.x * w1 + v2.x * w2 + v3.x * w3 + v4.x * w4;
        o.y = v1.y * w1 + v2.y * w2 + v3.y * w3 + v4.y * w4;
        o.z = v1.z * w1 + v2.z * w2 + v3.z * w3 + v4.z * w4;
        o.w = v1.w * w1 + v2.w * w2 + v3.w * w3 + v4.w * w4;

        __stcs(out4 + (size_t)(point0 + p) * (GC / 4) + slot, o);

        __syncthreads();                        // stage s fully consumed
        if (tid < 4 && it + STAGES < NITER) issue4(it + STAGES);
    }
}

extern "C" void kernel_launch(void* const* d_in, const int* in_sizes, int n_in,
                              void* d_out, int out_size)
{
    const float* in_tensor = (const float*)d_in[0];
    const float* indices   = (const float*)d_in[1];
    float*       out       = (float*)d_out;

    const int blocks = (GB * GP) / PPC;   // 131072/32 = 4096
    grid_sample_tma<<<blocks, NTHREADS>>>(in_tensor, indices, out);
}